// round 5
// baseline (speedup 1.0000x reference)
#include <cuda_runtime.h>
#include <math.h>
#include <stdint.h>

// Problem constants (GridPool, N=300000, B=4, C_IN=64, C_OUT=128, M=128, GRID=0.5)
#define NPTS   300000
#define CIN    64
#define COUT   128
#define NSCN   4
#define MDIM   128
#define KSIZE  (NSCN*MDIM*MDIM*MDIM)   // 8,388,608 keys
#define NWORDS (KSIZE/32)              // 262,144 bitmap words
#define GRIDSZ 0.5f
#define BN_EPS 1e-5f

// bit-scan geometry: 64 blocks x 256 threads x 16 words
#define BS_BLK   256
#define BS_ITEMS 16
#define BS_CHUNK (BS_BLK*BS_ITEMS)     // 4096 words
#define BS_NB    (NWORDS/BS_CHUNK)     // 64

// count-scan geometry over NPTS cluster slots
#define CS_CHUNK 4096
#define CS_NB    ((NPTS + CS_CHUNK - 1)/CS_CHUNK)   // 74

// GEMM smem strides (bank-conflict-free fragment loads)
#define GA_S 68       // A: 128 x 68
#define GB_S 136      // B: 64 x 136
#define GA_SZ (128*GA_S)   // 8704
#define GB_SZ (64*GB_S)    // 8704
#define GSM_U32 (2*GA_SZ + 2*GB_SZ)    // 34816 u32 = 139264 B

// ---------------- scratch (device globals) -----------------------------------
__device__ float    g_x[(size_t)NPTS*COUT];     // fc output
__device__ int      g_vkey[NPTS];
__device__ int      g_cluster[NPTS];
__device__ unsigned g_bits[NWORDS];             // presence bitmap (1 bit/key)
__device__ int      g_wordrank[NWORDS];         // exclusive popcount scan per word
__device__ int      g_ncl;                      // total cluster count
__device__ unsigned g_startbits[NSCN*3];        // per-scene min coord (float bits)
__device__ float    g_colstats[2*COUT];         // [0:128) sum, [128:256) sumsq
__device__ unsigned g_bsums[BS_NB];
__device__ unsigned g_boffs[BS_NB];
__device__ int      g_ccnt[NPTS];               // per-cluster point count
__device__ int      g_cstart[NPTS];             // per-cluster start (end after fill)
__device__ int      g_csums[CS_NB];
__device__ int      g_coffs[CS_NB];
__device__ int      g_plist[NPTS];              // point indices grouped by cluster

// ---------------- helpers ----------------------------------------------------
__device__ __forceinline__ int point_batch(int i, int o0, int o1, int o2) {
    return (i >= o0) + (i >= o1) + (i >= o2);
}

__device__ __forceinline__ void split_tf32(float f, unsigned& hi, unsigned& lo) {
    asm("cvt.rna.tf32.f32 %0, %1;" : "=r"(hi) : "f"(f));
    float r = f - __uint_as_float(hi);
    asm("cvt.rna.tf32.f32 %0, %1;" : "=r"(lo) : "f"(r));
}

#define MMA_TF32(C, A0, A1, A2, A3, B0, B1) \
    asm volatile("mma.sync.aligned.m16n8k8.row.col.f32.tf32.tf32.f32 " \
                 "{%0,%1,%2,%3},{%4,%5,%6,%7},{%8,%9},{%0,%1,%2,%3};" \
                 : "+f"((C)[0]), "+f"((C)[1]), "+f"((C)[2]), "+f"((C)[3]) \
                 : "r"(A0), "r"(A1), "r"(A2), "r"(A3), "r"(B0), "r"(B1))

template<typename T>
__device__ T block_exscan256(T v) {           // requires 256 threads
    unsigned lane = threadIdx.x & 31, wid = threadIdx.x >> 5;
    T x = v;
    #pragma unroll
    for (int o = 1; o < 32; o <<= 1) {
        T y = __shfl_up_sync(0xffffffffu, x, o);
        if (lane >= o) x += y;
    }
    __shared__ T ws[8];
    if (lane == 31) ws[wid] = x;
    __syncthreads();
    T woff = 0;
    #pragma unroll
    for (unsigned w = 0; w < 8; w++) woff += (w < wid) ? ws[w] : (T)0;
    __syncthreads();
    return woff + x - v;   // exclusive prefix of v
}

// ---------------- kernels ----------------------------------------------------
// per-scene min coordinate. coords >= 0 so uint-bit atomicMin works.
__global__ void k_scene_min(const float* __restrict__ coord,
                            const int* __restrict__ offset, int n) {
    __shared__ unsigned smin[NSCN*3];
    if (threadIdx.x < NSCN*3) smin[threadIdx.x] = 0xFFFFFFFFu;
    __syncthreads();
    int o0 = offset[0], o1 = offset[1], o2 = offset[2];
    for (int i = blockIdx.x*blockDim.x + threadIdx.x; i < n; i += gridDim.x*blockDim.x) {
        int b = point_batch(i, o0, o1, o2);
        #pragma unroll
        for (int d = 0; d < 3; d++)
            atomicMin(&smin[b*3+d], __float_as_uint(coord[(size_t)i*3+d]));
    }
    __syncthreads();
    if (threadIdx.x < NSCN*3) atomicMin(&g_startbits[threadIdx.x], smin[threadIdx.x]);
}

// voxel key per point + presence bit
__global__ void k_vkey(const float* __restrict__ coord,
                       const int* __restrict__ offset, int n) {
    int i = blockIdx.x*blockDim.x + threadIdx.x;
    if (i >= n) return;
    int o0 = offset[0], o1 = offset[1], o2 = offset[2];
    int b = point_batch(i, o0, o1, o2);
    float sx = __uint_as_float(g_startbits[b*3+0]);
    float sy = __uint_as_float(g_startbits[b*3+1]);
    float sz = __uint_as_float(g_startbits[b*3+2]);
    int vx = (int)floorf((coord[(size_t)i*3+0] - sx) / GRIDSZ);
    int vy = (int)floorf((coord[(size_t)i*3+1] - sy) / GRIDSZ);
    int vz = (int)floorf((coord[(size_t)i*3+2] - sz) / GRIDSZ);
    int key = ((b*MDIM + vx)*MDIM + vy)*MDIM + vz;
    g_vkey[i] = key;
    atomicOr(&g_bits[key >> 5], 1u << (key & 31));
}

// bit-scan pass 1: popcount sums per 4096-word chunk
__global__ void b_scan1() {
    int base = blockIdx.x*BS_CHUNK + threadIdx.x*BS_ITEMS;
    const uint4* p = (const uint4*)&g_bits[base];
    unsigned s = 0;
    #pragma unroll
    for (int j = 0; j < BS_ITEMS/4; j++) {
        uint4 v = p[j];
        s += __popc(v.x)+__popc(v.y)+__popc(v.z)+__popc(v.w);
    }
    __shared__ unsigned red[BS_BLK];
    red[threadIdx.x] = s; __syncthreads();
    for (int st = BS_BLK/2; st > 0; st >>= 1) {
        if (threadIdx.x < st) red[threadIdx.x] += red[threadIdx.x+st];
        __syncthreads();
    }
    if (threadIdx.x == 0) g_bsums[blockIdx.x] = red[0];
}

// bit-scan pass 2: exclusive scan of 64 block sums (single warp) + total
__global__ void b_scan2() {
    int t = threadIdx.x;                 // 32 threads
    unsigned v0 = g_bsums[2*t], v1 = g_bsums[2*t+1];
    unsigned s = v0 + v1, x = s;
    #pragma unroll
    for (int o = 1; o < 32; o <<= 1) {
        unsigned y = __shfl_up_sync(0xffffffffu, x, o);
        if (t >= o) x += y;
    }
    unsigned e = x - s;                  // exclusive
    g_boffs[2*t]   = e;
    g_boffs[2*t+1] = e + v0;
    if (t == 31) g_ncl = (int)(e + s);
}

// bit-scan pass 3: per-word exclusive rank
__global__ void b_scan3() {
    int base = blockIdx.x*BS_CHUNK + threadIdx.x*BS_ITEMS;
    unsigned pc[BS_ITEMS];
    const uint4* p = (const uint4*)&g_bits[base];
    unsigned s = 0;
    #pragma unroll
    for (int j = 0; j < BS_ITEMS/4; j++) {
        uint4 q = p[j];
        pc[j*4+0]=__popc(q.x); pc[j*4+1]=__popc(q.y);
        pc[j*4+2]=__popc(q.z); pc[j*4+3]=__popc(q.w);
        s += pc[j*4+0]+pc[j*4+1]+pc[j*4+2]+pc[j*4+3];
    }
    unsigned run = block_exscan256<unsigned>(s) + g_boffs[blockIdx.x];
    #pragma unroll
    for (int j = 0; j < BS_ITEMS; j++) { g_wordrank[base+j] = (int)run; run += pc[j]; }
}

// 3xTF32 tensor-core GEMM: x[n,128] = feat[n,64] @ W[64,128] (+ fused col stats)
// Block: 256 thr (8 warps as 4(M) x 2(N)), tile 128x128, K=64 in 8 k8 steps.
__global__ void __launch_bounds__(256, 1)
k_gemm(const float* __restrict__ feat, const float* __restrict__ Wm, int n) {
    extern __shared__ unsigned smu[];
    unsigned* Ahi = smu;
    unsigned* Alo = smu + GA_SZ;
    unsigned* Bhi = smu + 2*GA_SZ;
    unsigned* Blo = smu + 2*GA_SZ + GB_SZ;
    int tid = threadIdx.x;
    int row0 = blockIdx.x*128;

    // load A tile (zero-padded) as tf32 hi/lo
    const float4* f4 = (const float4*)feat;
    for (int s = tid; s < 128*16; s += 256) {
        int r = s >> 4, c4 = s & 15;
        int gr = row0 + r;
        float4 v = (gr < n) ? f4[(size_t)gr*16 + c4] : make_float4(0.f,0.f,0.f,0.f);
        int o = r*GA_S + c4*4;
        split_tf32(v.x, Ahi[o+0], Alo[o+0]);
        split_tf32(v.y, Ahi[o+1], Alo[o+1]);
        split_tf32(v.z, Ahi[o+2], Alo[o+2]);
        split_tf32(v.w, Ahi[o+3], Alo[o+3]);
    }
    // load B tile (64x128) as tf32 hi/lo
    const float4* w4 = (const float4*)Wm;
    for (int s = tid; s < 64*32; s += 256) {
        int r = s >> 5, c4 = s & 31;
        float4 v = w4[r*32 + c4];
        int o = r*GB_S + c4*4;
        split_tf32(v.x, Bhi[o+0], Blo[o+0]);
        split_tf32(v.y, Bhi[o+1], Blo[o+1]);
        split_tf32(v.z, Bhi[o+2], Blo[o+2]);
        split_tf32(v.w, Bhi[o+3], Blo[o+3]);
    }
    __syncthreads();

    int lane = tid & 31, wid = tid >> 5;
    int warp_m = wid >> 1, warp_n = wid & 1;
    int lr = lane >> 2, lc = lane & 3;

    float acc[2][8][4];
    #pragma unroll
    for (int mt = 0; mt < 2; mt++)
        #pragma unroll
        for (int nt = 0; nt < 8; nt++)
            #pragma unroll
            for (int q = 0; q < 4; q++) acc[mt][nt][q] = 0.f;

    int aoff0 = (warp_m*32 + lr)*GA_S + lc;
    int boff0 = lc*GB_S + warp_n*64 + lr;

    #pragma unroll
    for (int k = 0; k < 8; k++) {
        unsigned ah[2][4], al[2][4];
        #pragma unroll
        for (int mt = 0; mt < 2; mt++) {
            int ao = aoff0 + mt*(16*GA_S) + k*8;
            ah[mt][0] = Ahi[ao];           al[mt][0] = Alo[ao];
            ah[mt][1] = Ahi[ao + 8*GA_S];  al[mt][1] = Alo[ao + 8*GA_S];
            ah[mt][2] = Ahi[ao + 4];       al[mt][2] = Alo[ao + 4];
            ah[mt][3] = Ahi[ao + 8*GA_S+4];al[mt][3] = Alo[ao + 8*GA_S+4];
        }
        #pragma unroll
        for (int nt = 0; nt < 8; nt++) {
            int bo = boff0 + k*8*GB_S + nt*8;
            unsigned bh0 = Bhi[bo], bh1 = Bhi[bo + 4*GB_S];
            unsigned bl0 = Blo[bo], bl1 = Blo[bo + 4*GB_S];
            #pragma unroll
            for (int mt = 0; mt < 2; mt++) {
                MMA_TF32(acc[mt][nt], al[mt][0],al[mt][1],al[mt][2],al[mt][3], bh0, bh1);
                MMA_TF32(acc[mt][nt], ah[mt][0],ah[mt][1],ah[mt][2],ah[mt][3], bl0, bl1);
                MMA_TF32(acc[mt][nt], ah[mt][0],ah[mt][1],ah[mt][2],ah[mt][3], bh0, bh1);
            }
        }
    }
    __syncthreads();   // done with smem tiles

    // store x + fused column sum/sumsq
    float* red = (float*)smu;           // 256 floats: [0:128) sum, [128:256) sq
    red[tid] = 0.f;
    __syncthreads();

    #pragma unroll
    for (int nt = 0; nt < 8; nt++) {
        int colg = warp_n*64 + nt*8 + 2*lc;
        float sA = 0.f, sB = 0.f, qA = 0.f, qB = 0.f;
        #pragma unroll
        for (int mt = 0; mt < 2; mt++) {
            float c0 = acc[mt][nt][0], c1 = acc[mt][nt][1];
            float c2 = acc[mt][nt][2], c3 = acc[mt][nt][3];
            int rowg = row0 + warp_m*32 + mt*16 + lr;
            if (rowg < n)     *(float2*)&g_x[(size_t)rowg*COUT + colg]     = make_float2(c0, c1);
            if (rowg + 8 < n) *(float2*)&g_x[(size_t)(rowg+8)*COUT + colg] = make_float2(c2, c3);
            sA += c0 + c2;        sB += c1 + c3;       // padded rows give 0 (A zero-padded)
            qA += c0*c0 + c2*c2;  qB += c1*c1 + c3*c3;
        }
        // reduce over lr (lanes differing in bits [2:5))
        #pragma unroll
        for (int o = 4; o < 32; o <<= 1) {
            sA += __shfl_xor_sync(0xffffffffu, sA, o);
            sB += __shfl_xor_sync(0xffffffffu, sB, o);
            qA += __shfl_xor_sync(0xffffffffu, qA, o);
            qB += __shfl_xor_sync(0xffffffffu, qB, o);
        }
        if (lr == 0) {
            atomicAdd(&red[colg],         sA);
            atomicAdd(&red[colg+1],       sB);
            atomicAdd(&red[COUT + colg],  qA);
            atomicAdd(&red[COUT + colg+1],qB);
        }
    }
    __syncthreads();
    if (tid < 2*COUT) atomicAdd(&g_colstats[tid], red[tid]);
}

// cluster id per point (rank via bitmap popcount) + per-cluster counts
__global__ void k_assign(float* __restrict__ oClus, int n) {
    int i = blockIdx.x*blockDim.x + threadIdx.x;
    if (i >= n) return;
    int key = g_vkey[i];
    unsigned w = g_bits[key >> 5];
    int c = g_wordrank[key >> 5] + __popc(w & ((1u << (key & 31)) - 1u));
    g_cluster[i] = c;
    oClus[i] = (float)c;
    atomicAdd(&g_ccnt[c], 1);
}

// counting-sort scans over NPTS cluster slots
__global__ void c_scan1(int n) {
    int base = blockIdx.x*CS_CHUNK + threadIdx.x*16;
    int s = 0;
    #pragma unroll
    for (int j = 0; j < 16; j++) { int i = base+j; s += (i < n) ? g_ccnt[i] : 0; }
    __shared__ int red[256];
    red[threadIdx.x] = s; __syncthreads();
    for (int st = 128; st > 0; st >>= 1) {
        if (threadIdx.x < st) red[threadIdx.x] += red[threadIdx.x+st];
        __syncthreads();
    }
    if (threadIdx.x == 0) g_csums[blockIdx.x] = red[0];
}

__global__ void c_scan2() {                  // 1 block, 128 threads >= CS_NB
    __shared__ int s[128];
    int t = threadIdx.x;
    int v = (t < CS_NB) ? g_csums[t] : 0;
    s[t] = v; __syncthreads();
    #pragma unroll
    for (int o = 1; o < 128; o <<= 1) {
        int y = (t >= o) ? s[t-o] : 0;
        __syncthreads();
        s[t] += y;
        __syncthreads();
    }
    if (t < CS_NB) g_coffs[t] = s[t] - v;    // exclusive
}

__global__ void c_scan3(int n) {
    int base = blockIdx.x*CS_CHUNK + threadIdx.x*16;
    int v[16];
    int s = 0;
    #pragma unroll
    for (int j = 0; j < 16; j++) { int i = base+j; v[j] = (i < n) ? g_ccnt[i] : 0; s += v[j]; }
    int run = block_exscan256<int>(s) + g_coffs[blockIdx.x];
    #pragma unroll
    for (int j = 0; j < 16; j++) { int i = base+j; if (i < n) g_cstart[i] = run; run += v[j]; }
}

// fill point lists (mutates g_cstart -> segment end)
__global__ void k_fill(int n) {
    int i = blockIdx.x*blockDim.x + threadIdx.x;
    if (i >= n) return;
    int c = g_cluster[i];
    int slot = atomicAdd(&g_cstart[c], 1);
    g_plist[slot] = i;
}

// one block per cluster: feature max, coord mean, count, batch — no atomics
__global__ void k_gather(const float* __restrict__ coord,
                         const int* __restrict__ offset,
                         const float* __restrict__ gamma,
                         const float* __restrict__ beta,
                         float* __restrict__ oCoord, float* __restrict__ oFeat,
                         float* __restrict__ oCnt, float* __restrict__ oBatch, int n) {
    int j = threadIdx.x;            // 128 threads
    int ncl = g_ncl;
    // BN fold (was k_meanvar): y = a*x + bb
    float inv_n = 1.f / (float)n;
    float mean = g_colstats[j] * inv_n;
    float var  = g_colstats[COUT + j] * inv_n - mean*mean;
    float a    = gamma[j] * rsqrtf(var + BN_EPS);
    float bb   = beta[j] - a*mean;
    int o0 = offset[0], o1 = offset[1], o2 = offset[2];

    for (int c = blockIdx.x; c < n; c += gridDim.x) {
        if (c < ncl) {
            int cnt = g_ccnt[c];
            int end = g_cstart[c];          // start+cnt after k_fill
            int start = end - cnt;
            float m0 = 0.f, m1 = 0.f;       // ReLU identity
            int p = 0;
            for (; p + 1 < cnt; p += 2) {
                int i0 = g_plist[start+p];
                int i1 = g_plist[start+p+1];
                float y0 = a * g_x[(size_t)i0*COUT + j] + bb;
                float y1 = a * g_x[(size_t)i1*COUT + j] + bb;
                m0 = fmaxf(m0, y0);
                m1 = fmaxf(m1, y1);
            }
            if (p < cnt) {
                int i0 = g_plist[start+p];
                m0 = fmaxf(m0, a * g_x[(size_t)i0*COUT + j] + bb);
            }
            oFeat[(size_t)c*COUT + j] = fmaxf(m0, m1);
            if (j < 3) {
                float s = 0.f;
                for (int q = 0; q < cnt; q++) {
                    int i = g_plist[start+q];
                    s += coord[(size_t)i*3 + j];
                }
                oCoord[(size_t)c*3 + j] = s / (float)cnt;
            }
            if (j == 0) {
                oCnt[c] = (float)cnt;
                int i0 = g_plist[start];
                oBatch[c] = (float)point_batch(i0, o0, o1, o2);
            }
        } else {
            oFeat[(size_t)c*COUT + j] = 0.f;
            if (j < 3) oCoord[(size_t)c*3 + j] = 0.f;
            if (j == 0) { oCnt[c] = 0.f; oBatch[c] = 2147483648.0f; }
        }
    }
}

// ---------------- launch -----------------------------------------------------
extern "C" void kernel_launch(void* const* d_in, const int* in_sizes, int n_in,
                              void* d_out, int out_size) {
    const float* coord  = (const float*)d_in[0];
    const float* feat   = (const float*)d_in[1];
    const int*   offset = (const int*)  d_in[2];
    const float* Wm     = (const float*)d_in[3];
    const float* gamma  = (const float*)d_in[4];
    const float* beta   = (const float*)d_in[5];
    const int n = in_sizes[0] / 3;

    float* out    = (float*)d_out;
    float* oCoord = out;
    float* oFeat  = out + (size_t)3*n;
    float* oClus  = out + (size_t)131*n;
    float* oCnt   = out + (size_t)132*n;
    float* oBatch = out + (size_t)133*n;

    void *pBits, *pStart, *pStats, *pCcnt;
    cudaGetSymbolAddress(&pBits,  g_bits);
    cudaGetSymbolAddress(&pStart, g_startbits);
    cudaGetSymbolAddress(&pStats, g_colstats);
    cudaGetSymbolAddress(&pCcnt,  g_ccnt);

    cudaMemsetAsync(pBits,  0,    (size_t)NWORDS*4);
    cudaMemsetAsync(pStart, 0xFF, NSCN*3*4);
    cudaMemsetAsync(pStats, 0,    2*COUT*4);
    cudaMemsetAsync(pCcnt,  0,    (size_t)NPTS*4);

    int tpb = 256;
    int nb  = (n + tpb - 1) / tpb;

    k_scene_min<<<512, tpb>>>(coord, offset, n);
    k_vkey<<<nb, tpb>>>(coord, offset, n);
    b_scan1<<<BS_NB, BS_BLK>>>();
    b_scan2<<<1, 32>>>();
    b_scan3<<<BS_NB, BS_BLK>>>();

    static bool attr_set = false;
    size_t smem = (size_t)GSM_U32 * 4;   // 139264 B
    if (!attr_set) {
        cudaFuncSetAttribute(k_gemm, cudaFuncAttributeMaxDynamicSharedMemorySize, (int)smem);
        attr_set = true;
    }
    k_gemm<<<(n + 127)/128, 256, smem>>>(feat, Wm, n);

    k_assign<<<nb, tpb>>>(oClus, n);
    c_scan1<<<CS_NB, 256>>>(n);
    c_scan2<<<1, 128>>>();
    c_scan3<<<CS_NB, 256>>>(n);
    k_fill<<<nb, tpb>>>(n);

    k_gather<<<4096, COUT>>>(coord, offset, gamma, beta,
                             oCoord, oFeat, oCnt, oBatch, n);
}

// round 6
// speedup vs baseline: 1.1905x; 1.1905x over previous
#include <cuda_runtime.h>
#include <math.h>
#include <stdint.h>

// Problem constants (GridPool, N=300000, B=4, C_IN=64, C_OUT=128, M=128, GRID=0.5)
#define NPTS   300000
#define CIN    64
#define COUT   128
#define NSCN   4
#define MDIM   128
#define KSIZE  (NSCN*MDIM*MDIM*MDIM)   // 8,388,608 keys
#define NWORDS (KSIZE/32)              // 262,144 bitmap words
#define GRIDSZ 0.5f
#define BN_EPS 1e-5f

// bit-scan geometry: 64 blocks x 256 threads x 16 words
#define BS_BLK   256
#define BS_ITEMS 16
#define BS_CHUNK (BS_BLK*BS_ITEMS)     // 4096 words
#define BS_NB    (NWORDS/BS_CHUNK)     // 64

// count-scan geometry over NPTS cluster slots
#define CS_CHUNK 4096
#define CS_NB    ((NPTS + CS_CHUNK - 1)/CS_CHUNK)   // 74

// ---------------- scratch (device globals) -----------------------------------
__device__ float    g_x[(size_t)NPTS*COUT];     // fc output
__device__ int      g_vkey[NPTS];
__device__ int      g_cluster[NPTS];
__device__ unsigned g_bits[NWORDS];             // presence bitmap (1 bit/key)
__device__ int      g_wordrank[NWORDS];         // exclusive popcount scan per word
__device__ int      g_ncl;                      // total cluster count
__device__ unsigned g_startbits[NSCN*3];        // per-scene min coord (float bits)
__device__ float    g_colstats[2*COUT];         // [0:128) sum, [128:256) sumsq
__device__ unsigned g_bsums[BS_NB];
__device__ unsigned g_boffs[BS_NB];
__device__ int      g_ccnt[NPTS];               // per-cluster point count
__device__ int      g_cstart[NPTS];             // per-cluster start (end after fill)
__device__ int      g_csums[CS_NB];
__device__ int      g_coffs[CS_NB];
__device__ int      g_plist[NPTS];              // point indices grouped by cluster

// ---------------- helpers ----------------------------------------------------
__device__ __forceinline__ int point_batch(int i, int o0, int o1, int o2) {
    return (i >= o0) + (i >= o1) + (i >= o2);
}

template<typename T>
__device__ T block_exscan256(T v) {           // requires 256 threads
    unsigned lane = threadIdx.x & 31, wid = threadIdx.x >> 5;
    T x = v;
    #pragma unroll
    for (int o = 1; o < 32; o <<= 1) {
        T y = __shfl_up_sync(0xffffffffu, x, o);
        if (lane >= o) x += y;
    }
    __shared__ T ws[8];
    if (lane == 31) ws[wid] = x;
    __syncthreads();
    T woff = 0;
    #pragma unroll
    for (unsigned w = 0; w < 8; w++) woff += (w < wid) ? ws[w] : (T)0;
    __syncthreads();
    return woff + x - v;   // exclusive prefix of v
}

// ---------------- kernels ----------------------------------------------------
// per-scene min coordinate. coords >= 0 so uint-bit atomicMin works.
__global__ void k_scene_min(const float* __restrict__ coord,
                            const int* __restrict__ offset, int n) {
    __shared__ unsigned smin[NSCN*3];
    if (threadIdx.x < NSCN*3) smin[threadIdx.x] = 0xFFFFFFFFu;
    __syncthreads();
    int o0 = offset[0], o1 = offset[1], o2 = offset[2];
    for (int i = blockIdx.x*blockDim.x + threadIdx.x; i < n; i += gridDim.x*blockDim.x) {
        int b = point_batch(i, o0, o1, o2);
        #pragma unroll
        for (int d = 0; d < 3; d++)
            atomicMin(&smin[b*3+d], __float_as_uint(coord[(size_t)i*3+d]));
    }
    __syncthreads();
    if (threadIdx.x < NSCN*3) atomicMin(&g_startbits[threadIdx.x], smin[threadIdx.x]);
}

// voxel key per point + presence bit
__global__ void k_vkey(const float* __restrict__ coord,
                       const int* __restrict__ offset, int n) {
    int i = blockIdx.x*blockDim.x + threadIdx.x;
    if (i >= n) return;
    int o0 = offset[0], o1 = offset[1], o2 = offset[2];
    int b = point_batch(i, o0, o1, o2);
    float sx = __uint_as_float(g_startbits[b*3+0]);
    float sy = __uint_as_float(g_startbits[b*3+1]);
    float sz = __uint_as_float(g_startbits[b*3+2]);
    int vx = (int)floorf((coord[(size_t)i*3+0] - sx) / GRIDSZ);
    int vy = (int)floorf((coord[(size_t)i*3+1] - sy) / GRIDSZ);
    int vz = (int)floorf((coord[(size_t)i*3+2] - sz) / GRIDSZ);
    int key = ((b*MDIM + vx)*MDIM + vy)*MDIM + vz;
    g_vkey[i] = key;
    atomicOr(&g_bits[key >> 5], 1u << (key & 31));
}

// bit-scan pass 1: popcount sums per 4096-word chunk
__global__ void b_scan1() {
    int base = blockIdx.x*BS_CHUNK + threadIdx.x*BS_ITEMS;
    const uint4* p = (const uint4*)&g_bits[base];
    unsigned s = 0;
    #pragma unroll
    for (int j = 0; j < BS_ITEMS/4; j++) {
        uint4 v = p[j];
        s += __popc(v.x)+__popc(v.y)+__popc(v.z)+__popc(v.w);
    }
    __shared__ unsigned red[BS_BLK];
    red[threadIdx.x] = s; __syncthreads();
    for (int st = BS_BLK/2; st > 0; st >>= 1) {
        if (threadIdx.x < st) red[threadIdx.x] += red[threadIdx.x+st];
        __syncthreads();
    }
    if (threadIdx.x == 0) g_bsums[blockIdx.x] = red[0];
}

// bit-scan pass 2: exclusive scan of 64 block sums (single warp) + total
__global__ void b_scan2() {
    int t = threadIdx.x;                 // 32 threads
    unsigned v0 = g_bsums[2*t], v1 = g_bsums[2*t+1];
    unsigned s = v0 + v1, x = s;
    #pragma unroll
    for (int o = 1; o < 32; o <<= 1) {
        unsigned y = __shfl_up_sync(0xffffffffu, x, o);
        if (t >= o) x += y;
    }
    unsigned e = x - s;                  // exclusive
    g_boffs[2*t]   = e;
    g_boffs[2*t+1] = e + v0;
    if (t == 31) g_ncl = (int)(e + s);
}

// bit-scan pass 3: per-word exclusive rank
__global__ void b_scan3() {
    int base = blockIdx.x*BS_CHUNK + threadIdx.x*BS_ITEMS;
    unsigned pc[BS_ITEMS];
    const uint4* p = (const uint4*)&g_bits[base];
    unsigned s = 0;
    #pragma unroll
    for (int j = 0; j < BS_ITEMS/4; j++) {
        uint4 q = p[j];
        pc[j*4+0]=__popc(q.x); pc[j*4+1]=__popc(q.y);
        pc[j*4+2]=__popc(q.z); pc[j*4+3]=__popc(q.w);
        s += pc[j*4+0]+pc[j*4+1]+pc[j*4+2]+pc[j*4+3];
    }
    unsigned run = block_exscan256<unsigned>(s) + g_boffs[blockIdx.x];
    #pragma unroll
    for (int j = 0; j < BS_ITEMS; j++) { g_wordrank[base+j] = (int)run; run += pc[j]; }
}

// fp32 GEMM with fused column sum/sumsq epilogue (R2 version — known 90us)
__global__ void k_gemm(const float* __restrict__ feat, const float* __restrict__ Wm, int n) {
    extern __shared__ float sm[];
    float* As = sm;                 // 128 x 65 (padded)
    float* Bs = sm + 128*65;        // 64 x 128
    int row0 = blockIdx.x*128;

    for (int t = threadIdx.x; t < 128*64; t += 256) {
        int r = t >> 6, c = t & 63;
        int gr = row0 + r;
        As[r*65+c] = (gr < n) ? feat[(size_t)gr*CIN + c] : 0.f;
    }
    {
        float4* B4 = (float4*)Bs;
        const float4* W4 = (const float4*)Wm;
        for (int t = threadIdx.x; t < (CIN*COUT)/4; t += 256) B4[t] = W4[t];
    }
    __syncthreads();

    int tx = threadIdx.x & 15, ty = threadIdx.x >> 4;
    float acc[8][8];
    #pragma unroll
    for (int i = 0; i < 8; i++)
        #pragma unroll
        for (int j = 0; j < 8; j++) acc[i][j] = 0.f;

    #pragma unroll 8
    for (int k = 0; k < CIN; k++) {
        float ra[8], rb[8];
        #pragma unroll
        for (int i = 0; i < 8; i++) ra[i] = As[(16*i+ty)*65 + k];
        #pragma unroll
        for (int j = 0; j < 8; j++) rb[j] = Bs[k*COUT + 16*j+tx];
        #pragma unroll
        for (int i = 0; i < 8; i++)
            #pragma unroll
            for (int j = 0; j < 8; j++) acc[i][j] += ra[i]*rb[j];
    }
    #pragma unroll
    for (int i = 0; i < 8; i++) {
        int gr = row0 + 16*i + ty;
        if (gr < n) {
            #pragma unroll
            for (int j = 0; j < 8; j++)
                g_x[(size_t)gr*COUT + 16*j+tx] = acc[i][j];
        }
    }

    // fused column stats: rows beyond n contribute 0 (As zero-padded)
    __syncthreads();                // done reading As/Bs
    float* rsum = sm;               // 128 cols x 16 ty
    float* rsq  = sm + 2048;
    #pragma unroll
    for (int j = 0; j < 8; j++) {
        float s = 0.f, q = 0.f;
        #pragma unroll
        for (int i = 0; i < 8; i++) { float v = acc[i][j]; s += v; q += v*v; }
        rsum[(16*j+tx)*16 + ty] = s;
        rsq [(16*j+tx)*16 + ty] = q;
    }
    __syncthreads();
    if (threadIdx.x < COUT) {
        float s = 0.f, q = 0.f;
        #pragma unroll
        for (int t = 0; t < 16; t++) { s += rsum[threadIdx.x*16+t]; q += rsq[threadIdx.x*16+t]; }
        atomicAdd(&g_colstats[threadIdx.x], s);
        atomicAdd(&g_colstats[COUT + threadIdx.x], q);
    }
}

// cluster id per point (rank via bitmap popcount) + per-cluster counts
__global__ void k_assign(float* __restrict__ oClus, int n) {
    int i = blockIdx.x*blockDim.x + threadIdx.x;
    if (i >= n) return;
    int key = g_vkey[i];
    unsigned w = g_bits[key >> 5];
    int c = g_wordrank[key >> 5] + __popc(w & ((1u << (key & 31)) - 1u));
    g_cluster[i] = c;
    oClus[i] = (float)c;
    atomicAdd(&g_ccnt[c], 1);
}

// counting-sort scans over NPTS cluster slots
__global__ void c_scan1(int n) {
    int base = blockIdx.x*CS_CHUNK + threadIdx.x*16;
    int s = 0;
    #pragma unroll
    for (int j = 0; j < 16; j++) { int i = base+j; s += (i < n) ? g_ccnt[i] : 0; }
    __shared__ int red[256];
    red[threadIdx.x] = s; __syncthreads();
    for (int st = 128; st > 0; st >>= 1) {
        if (threadIdx.x < st) red[threadIdx.x] += red[threadIdx.x+st];
        __syncthreads();
    }
    if (threadIdx.x == 0) g_csums[blockIdx.x] = red[0];
}

__global__ void c_scan2() {                  // 1 block, 128 threads >= CS_NB
    __shared__ int s[128];
    int t = threadIdx.x;
    int v = (t < CS_NB) ? g_csums[t] : 0;
    s[t] = v; __syncthreads();
    #pragma unroll
    for (int o = 1; o < 128; o <<= 1) {
        int y = (t >= o) ? s[t-o] : 0;
        __syncthreads();
        s[t] += y;
        __syncthreads();
    }
    if (t < CS_NB) g_coffs[t] = s[t] - v;    // exclusive
}

__global__ void c_scan3(int n) {
    int base = blockIdx.x*CS_CHUNK + threadIdx.x*16;
    int v[16];
    int s = 0;
    #pragma unroll
    for (int j = 0; j < 16; j++) { int i = base+j; v[j] = (i < n) ? g_ccnt[i] : 0; s += v[j]; }
    int run = block_exscan256<int>(s) + g_coffs[blockIdx.x];
    #pragma unroll
    for (int j = 0; j < 16; j++) { int i = base+j; if (i < n) g_cstart[i] = run; run += v[j]; }
}

// fill point lists (mutates g_cstart -> segment end)
__global__ void k_fill(int n) {
    int i = blockIdx.x*blockDim.x + threadIdx.x;
    if (i >= n) return;
    int c = g_cluster[i];
    int slot = atomicAdd(&g_cstart[c], 1);
    g_plist[slot] = i;
}

// sentinel fill for batch_out (segment_min identity for empty segments)
__global__ void k_fillbatch(float* __restrict__ oBatch, int n) {
    int i = blockIdx.x*blockDim.x + threadIdx.x;
    if (i < n) oBatch[i] = 2147483648.0f;   // (float)INT32_MAX
}

// one block per REAL cluster only: feature max, coord mean, count, batch.
// Padded clusters are handled by overlapped memsets + k_fillbatch.
__global__ void k_gather(const float* __restrict__ coord,
                         const int* __restrict__ offset,
                         const float* __restrict__ gamma,
                         const float* __restrict__ beta,
                         float* __restrict__ oCoord, float* __restrict__ oFeat,
                         float* __restrict__ oCnt, float* __restrict__ oBatch, int n) {
    int j = threadIdx.x;            // 128 threads
    int ncl = g_ncl;
    // BN fold: y = a*x + bb
    float inv_n = 1.f / (float)n;
    float mean = g_colstats[j] * inv_n;
    float var  = g_colstats[COUT + j] * inv_n - mean*mean;
    float a    = gamma[j] * rsqrtf(var + BN_EPS);
    float bb   = beta[j] - a*mean;
    int o0 = offset[0], o1 = offset[1], o2 = offset[2];

    for (int c = blockIdx.x; c < ncl; c += gridDim.x) {
        int cnt = g_ccnt[c];
        int end = g_cstart[c];          // start+cnt after k_fill
        int start = end - cnt;
        float m0 = 0.f, m1 = 0.f;       // ReLU identity
        int p = 0;
        for (; p + 1 < cnt; p += 2) {
            int i0 = g_plist[start+p];
            int i1 = g_plist[start+p+1];
            float y0 = a * g_x[(size_t)i0*COUT + j] + bb;
            float y1 = a * g_x[(size_t)i1*COUT + j] + bb;
            m0 = fmaxf(m0, y0);
            m1 = fmaxf(m1, y1);
        }
        if (p < cnt) {
            int i0 = g_plist[start+p];
            m0 = fmaxf(m0, a * g_x[(size_t)i0*COUT + j] + bb);
        }
        oFeat[(size_t)c*COUT + j] = fmaxf(m0, m1);
        if (j < 3) {
            float s = 0.f;
            for (int q = 0; q < cnt; q++) {
                int i = g_plist[start+q];
                s += coord[(size_t)i*3 + j];
            }
            oCoord[(size_t)c*3 + j] = s / (float)cnt;
        }
        if (j == 0) {
            oCnt[c] = (float)cnt;
            int i0 = g_plist[start];
            oBatch[c] = (float)point_batch(i0, o0, o1, o2);
        }
    }
}

// ---------------- launch -----------------------------------------------------
extern "C" void kernel_launch(void* const* d_in, const int* in_sizes, int n_in,
                              void* d_out, int out_size) {
    const float* coord  = (const float*)d_in[0];
    const float* feat   = (const float*)d_in[1];
    const int*   offset = (const int*)  d_in[2];
    const float* Wm     = (const float*)d_in[3];
    const float* gamma  = (const float*)d_in[4];
    const float* beta   = (const float*)d_in[5];
    const int n = in_sizes[0] / 3;

    float* out    = (float*)d_out;
    float* oCoord = out;
    float* oFeat  = out + (size_t)3*n;
    float* oClus  = out + (size_t)131*n;
    float* oCnt   = out + (size_t)132*n;
    float* oBatch = out + (size_t)133*n;

    void *pBits, *pStart, *pStats, *pCcnt;
    cudaGetSymbolAddress(&pBits,  g_bits);
    cudaGetSymbolAddress(&pStart, g_startbits);
    cudaGetSymbolAddress(&pStats, g_colstats);
    cudaGetSymbolAddress(&pCcnt,  g_ccnt);

    // one-time resources (same pattern as cudaFuncSetAttribute below)
    static cudaStream_t s2 = nullptr, s3 = nullptr;
    static cudaEvent_t evRoot = nullptr, ev2 = nullptr, ev3 = nullptr;
    static bool init_done = false;
    if (!init_done) {
        cudaStreamCreateWithFlags(&s2, cudaStreamNonBlocking);
        cudaStreamCreateWithFlags(&s3, cudaStreamNonBlocking);
        cudaEventCreateWithFlags(&evRoot, cudaEventDisableTiming);
        cudaEventCreateWithFlags(&ev2,    cudaEventDisableTiming);
        cudaEventCreateWithFlags(&ev3,    cudaEventDisableTiming);
        size_t smem = (128*65 + 64*128) * sizeof(float);   // 66 KB
        cudaFuncSetAttribute(k_gemm, cudaFuncAttributeMaxDynamicSharedMemorySize, (int)smem);
        init_done = true;
    }

    int tpb = 256;
    int nb  = (n + tpb - 1) / tpb;
    size_t smem = (128*65 + 64*128) * sizeof(float);

    // fork: s2 (GEMM chain) and s3 (output padding) branch off the captured stream
    cudaEventRecord(evRoot, 0);
    cudaStreamWaitEvent(s2, evRoot, 0);
    cudaStreamWaitEvent(s3, evRoot, 0);

    // ---- branch s2: GEMM + column stats ----
    cudaMemsetAsync(pStats, 0, 2*COUT*4, s2);
    k_gemm<<<(n + 127)/128, 256, smem, s2>>>(feat, Wm, n);
    cudaEventRecord(ev2, s2);

    // ---- branch s3: output padding (zeros + batch sentinel over full buffers) ----
    cudaMemsetAsync(oCoord, 0, (size_t)3*n*4,      s3);
    cudaMemsetAsync(oFeat,  0, (size_t)n*COUT*4,   s3);
    cudaMemsetAsync(oCnt,   0, (size_t)n*4,        s3);
    k_fillbatch<<<nb, tpb, 0, s3>>>(oBatch, n);
    cudaEventRecord(ev3, s3);

    // ---- main branch (captured stream): voxel chain ----
    cudaMemsetAsync(pBits,  0,    (size_t)NWORDS*4);
    cudaMemsetAsync(pStart, 0xFF, NSCN*3*4);
    cudaMemsetAsync(pCcnt,  0,    (size_t)NPTS*4);
    k_scene_min<<<512, tpb>>>(coord, offset, n);
    k_vkey<<<nb, tpb>>>(coord, offset, n);
    b_scan1<<<BS_NB, BS_BLK>>>();
    b_scan2<<<1, 32>>>();
    b_scan3<<<BS_NB, BS_BLK>>>();
    k_assign<<<nb, tpb>>>(oClus, n);
    c_scan1<<<CS_NB, 256>>>(n);
    c_scan2<<<1, 128>>>();
    c_scan3<<<CS_NB, 256>>>(n);
    k_fill<<<nb, tpb>>>(n);

    // join: gather needs GEMM output, colstats, and padded outputs
    cudaStreamWaitEvent(0, ev2, 0);
    cudaStreamWaitEvent(0, ev3, 0);
    k_gather<<<2048, COUT>>>(coord, offset, gamma, beta,
                             oCoord, oFeat, oCnt, oBatch, n);
}